// round 1
// baseline (speedup 1.0000x reference)
#include <cuda_runtime.h>

// Problem constants
#define T_  1024
#define B_  8
#define D_  1024
#define H_  16
#define HD_ 64
#define M_  (T_ * B_)   // 8192 rows for the projection GEMMs

// Scratch (device globals: no runtime allocation allowed)
__device__ float g_Q[M_ * D_];
__device__ float g_K[M_ * D_];
__device__ float g_V[M_ * D_];
__device__ float g_O[M_ * D_];

// ---------------------------------------------------------------------------
// GEMM: C[M,N] = A[M,K] @ W[N,K]^T + bias   (nn.Linear semantics)
// 128x128 tile, BK=8, 256 threads, 8x8 micro-tile per thread.
// ---------------------------------------------------------------------------
#define BM 128
#define BN 128
#define BK 8

__global__ __launch_bounds__(256) void sgemm_nt_bias(
    const float* __restrict__ A, const float* __restrict__ W,
    const float* __restrict__ bias, float* __restrict__ C,
    int M, int N, int K)
{
    __shared__ float As[BK][BM];
    __shared__ float Bs[BK][BN];

    const int tid = threadIdx.x;
    const int m0  = blockIdx.y * BM;
    const int n0  = blockIdx.x * BN;
    const int ty  = tid >> 4;       // 0..15
    const int tx  = tid & 15;       // 0..15
    const int lrow = tid >> 1;      // 0..127
    const int lk4  = (tid & 1) * 4; // 0 or 4

    float acc[8][8];
#pragma unroll
    for (int i = 0; i < 8; i++)
#pragma unroll
        for (int j = 0; j < 8; j++) acc[i][j] = 0.f;

    const float* Aptr = A + (size_t)(m0 + lrow) * K + lk4;
    const float* Wptr = W + (size_t)(n0 + lrow) * K + lk4;

    for (int k0 = 0; k0 < K; k0 += BK) {
        float4 a4 = *(const float4*)(Aptr + k0);
        float4 w4 = *(const float4*)(Wptr + k0);
        __syncthreads();
        As[lk4 + 0][lrow] = a4.x; As[lk4 + 1][lrow] = a4.y;
        As[lk4 + 2][lrow] = a4.z; As[lk4 + 3][lrow] = a4.w;
        Bs[lk4 + 0][lrow] = w4.x; Bs[lk4 + 1][lrow] = w4.y;
        Bs[lk4 + 2][lrow] = w4.z; Bs[lk4 + 3][lrow] = w4.w;
        __syncthreads();
#pragma unroll
        for (int kk = 0; kk < BK; kk++) {
            float4 a0 = *(const float4*)&As[kk][ty * 8];
            float4 a1 = *(const float4*)&As[kk][ty * 8 + 4];
            float4 b0 = *(const float4*)&Bs[kk][tx * 8];
            float4 b1 = *(const float4*)&Bs[kk][tx * 8 + 4];
            float a[8] = {a0.x, a0.y, a0.z, a0.w, a1.x, a1.y, a1.z, a1.w};
            float b[8] = {b0.x, b0.y, b0.z, b0.w, b1.x, b1.y, b1.z, b1.w};
#pragma unroll
            for (int i = 0; i < 8; i++)
#pragma unroll
                for (int j = 0; j < 8; j++) acc[i][j] += a[i] * b[j];
        }
    }

#pragma unroll
    for (int i = 0; i < 8; i++) {
        float* crow = C + (size_t)(m0 + ty * 8 + i) * N + n0 + tx * 8;
#pragma unroll
        for (int j4 = 0; j4 < 2; j4++) {
            float4 r;
            r.x = acc[i][j4 * 4 + 0] + bias[n0 + tx * 8 + j4 * 4 + 0];
            r.y = acc[i][j4 * 4 + 1] + bias[n0 + tx * 8 + j4 * 4 + 1];
            r.z = acc[i][j4 * 4 + 2] + bias[n0 + tx * 8 + j4 * 4 + 2];
            r.w = acc[i][j4 * 4 + 3] + bias[n0 + tx * 8 + j4 * 4 + 3];
            *(float4*)(crow + j4 * 4) = r;
        }
    }
}

// ---------------------------------------------------------------------------
// Flash attention (fp32, online softmax).
// Grid: (T/64, B*H). Block: 256 threads.
// Each query row is owned by 4 consecutive threads (lanes 0..3).
// Lane's key set for score j is kc = j*4 + lane; lane's output dims are
// float4 chunks (g*4+lane)*4 .. +3.  Smem rows padded to 68 floats so every
// float4 LDS pattern has <=4 distinct bank-disjoint addresses (broadcast).
// ---------------------------------------------------------------------------
#define BQ   64
#define BKV  64
#define KPAD 68
#define SMEM_FLASH (3 * BKV * KPAD * 4)   // Ks + Vs + Ps = 52224 bytes

__global__ __launch_bounds__(256) void flash_attn_kernel(
    const float* __restrict__ Q, const float* __restrict__ K,
    const float* __restrict__ V, float* __restrict__ O)
{
    extern __shared__ float sm[];
    float* Ks = sm;                    // [BKV][KPAD]
    float* Vs = sm + BKV * KPAD;       // [BKV][KPAD]
    float* Ps = sm + 2 * BKV * KPAD;   // [BQ][KPAD]

    const int tid  = threadIdx.x;
    const int row  = tid >> 2;         // 0..63 query row in tile
    const int lane = tid & 3;          // 0..3
    const int bh   = blockIdx.y;
    const int b    = bh / H_;
    const int h    = bh % H_;
    const int q0   = blockIdx.x * BQ;
    const float scale = 0.125f;        // 1/sqrt(64)

    // Q row in registers, pre-scaled
    float q[64];
    const float* qptr = Q + ((size_t)(q0 + row) * B_ + b) * D_ + h * HD_;
#pragma unroll
    for (int c = 0; c < 16; c++) {
        float4 v4 = *(const float4*)(qptr + c * 4);
        q[c * 4 + 0] = v4.x * scale;
        q[c * 4 + 1] = v4.y * scale;
        q[c * 4 + 2] = v4.z * scale;
        q[c * 4 + 3] = v4.w * scale;
    }

    float m = -1e30f, l = 0.f;
    float4 o[4];
#pragma unroll
    for (int g = 0; g < 4; g++) o[g] = make_float4(0.f, 0.f, 0.f, 0.f);

    for (int s0 = 0; s0 < T_; s0 += BKV) {
        __syncthreads();  // previous tile's smem reads done
        // Load K and V tiles: 64x64 floats each, 4 float4 per thread per tile
#pragma unroll
        for (int e = 0; e < 4; e++) {
            int lin = tid + e * 256;         // 0..1023 float4 index
            int r   = lin >> 4;              // 0..63
            int c4  = (lin & 15) * 4;        // 0..60
            size_t goff = ((size_t)(s0 + r) * B_ + b) * D_ + h * HD_ + c4;
            float4 kv = *(const float4*)(K + goff);
            float4 vv = *(const float4*)(V + goff);
            *(float4*)&Ks[r * KPAD + c4] = kv;
            *(float4*)&Vs[r * KPAD + c4] = vv;
        }
        __syncthreads();

        // S = q . K^T for this lane's 16 keys
        float p[16];
        float lm = -1e30f;
#pragma unroll
        for (int j = 0; j < 16; j++) {
            int kc = j * 4 + lane;
            const float* krow = &Ks[kc * KPAD];
            float s = 0.f;
#pragma unroll
            for (int c = 0; c < 16; c++) {
                float4 kv = *(const float4*)(krow + c * 4);
                s += q[c * 4 + 0] * kv.x + q[c * 4 + 1] * kv.y
                   + q[c * 4 + 2] * kv.z + q[c * 4 + 3] * kv.w;
            }
            p[j] = s;
            lm = fmaxf(lm, s);
        }
        // row max across 4 lanes
        lm = fmaxf(lm, __shfl_xor_sync(0xffffffffu, lm, 1));
        lm = fmaxf(lm, __shfl_xor_sync(0xffffffffu, lm, 2));
        float mnew  = fmaxf(m, lm);
        float alpha = __expf(m - mnew);
        float ls = 0.f;
#pragma unroll
        for (int j = 0; j < 16; j++) {
            p[j] = __expf(p[j] - mnew);
            ls += p[j];
        }
        ls += __shfl_xor_sync(0xffffffffu, ls, 1);
        ls += __shfl_xor_sync(0xffffffffu, ls, 2);
        l = l * alpha + ls;
        m = mnew;
#pragma unroll
        for (int g = 0; g < 4; g++) {
            o[g].x *= alpha; o[g].y *= alpha; o[g].z *= alpha; o[g].w *= alpha;
        }

        // Stage P row (lane writes its 16 keys at columns j*4+lane)
#pragma unroll
        for (int j = 0; j < 16; j++)
            Ps[row * KPAD + j * 4 + lane] = p[j];
        __syncwarp();

        // O += P @ V   (lane accumulates dims (g*4+lane)*4 .. +3)
#pragma unroll
        for (int k = 0; k < BKV; k++) {
            float pk = Ps[row * KPAD + k];
            const float* vrow = &Vs[k * KPAD];
#pragma unroll
            for (int g = 0; g < 4; g++) {
                float4 vv = *(const float4*)(vrow + (g * 4 + lane) * 4);
                o[g].x += pk * vv.x; o[g].y += pk * vv.y;
                o[g].z += pk * vv.z; o[g].w += pk * vv.w;
            }
        }
    }

    const float inv = 1.f / l;
    float* optr = O + ((size_t)(q0 + row) * B_ + b) * D_ + h * HD_;
#pragma unroll
    for (int g = 0; g < 4; g++) {
        float4 ov;
        ov.x = o[g].x * inv; ov.y = o[g].y * inv;
        ov.z = o[g].z * inv; ov.w = o[g].w * inv;
        *(float4*)(optr + (g * 4 + lane) * 4) = ov;
    }
}

// ---------------------------------------------------------------------------
extern "C" void kernel_launch(void* const* d_in, const int* in_sizes, int n_in,
                              void* d_out, int out_size)
{
    const float* x  = (const float*)d_in[0];
    const float* Wq = (const float*)d_in[1];
    const float* bq = (const float*)d_in[2];
    const float* Wk = (const float*)d_in[3];
    const float* bk = (const float*)d_in[4];
    const float* Wv = (const float*)d_in[5];
    const float* bv = (const float*)d_in[6];
    const float* Wo = (const float*)d_in[7];
    const float* bo = (const float*)d_in[8];
    float* out = (float*)d_out;

    float *Qb, *Kb, *Vb, *Ob;
    cudaGetSymbolAddress((void**)&Qb, g_Q);
    cudaGetSymbolAddress((void**)&Kb, g_K);
    cudaGetSymbolAddress((void**)&Vb, g_V);
    cudaGetSymbolAddress((void**)&Ob, g_O);

    dim3 gGemm(D_ / BN, M_ / BM);   // (8, 64)

    sgemm_nt_bias<<<gGemm, 256>>>(x, Wq, bq, Qb, M_, D_, D_);
    sgemm_nt_bias<<<gGemm, 256>>>(x, Wk, bk, Kb, M_, D_, D_);
    sgemm_nt_bias<<<gGemm, 256>>>(x, Wv, bv, Vb, M_, D_, D_);

    cudaFuncSetAttribute(flash_attn_kernel,
                         cudaFuncAttributeMaxDynamicSharedMemorySize, SMEM_FLASH);
    flash_attn_kernel<<<dim3(T_ / BQ, B_ * H_), 256, SMEM_FLASH>>>(Qb, Kb, Vb, Ob);

    sgemm_nt_bias<<<gGemm, 256>>>(Ob, Wo, bo, out, M_, D_, D_);
}

// round 2
// speedup vs baseline: 4.4729x; 4.4729x over previous
#include <cuda_runtime.h>

#define T_  1024
#define B_  8
#define D_  1024
#define H_  16
#define HD_ 64
#define M_  (T_ * B_)

// Scratch (device globals — no runtime allocation allowed)
__device__ float g_Q[M_ * D_];
__device__ float g_K[M_ * D_];
__device__ float g_V[M_ * D_];
__device__ float g_O[M_ * D_];

// ---------------------------------------------------------------------------
// Helpers
// ---------------------------------------------------------------------------
__device__ __forceinline__ unsigned f2tf(float f) {
    unsigned u;
    asm("cvt.rna.tf32.f32 %0, %1;" : "=r"(u) : "f"(f));
    return u;
}

__device__ __forceinline__ void mma_tf32(float d[4], const unsigned a[4],
                                         const unsigned b[2], const float c[4]) {
    asm volatile(
        "mma.sync.aligned.m16n8k8.row.col.f32.tf32.tf32.f32 "
        "{%0,%1,%2,%3}, {%4,%5,%6,%7}, {%8,%9}, {%10,%11,%12,%13};"
        : "=f"(d[0]), "=f"(d[1]), "=f"(d[2]), "=f"(d[3])
        : "r"(a[0]), "r"(a[1]), "r"(a[2]), "r"(a[3]),
          "r"(b[0]), "r"(b[1]),
          "f"(c[0]), "f"(c[1]), "f"(c[2]), "f"(c[3]));
}

__device__ __forceinline__ unsigned smem_u32(const void* p) {
    return (unsigned)__cvta_generic_to_shared(p);
}

// ---------------------------------------------------------------------------
// tf32 GEMM: C[M,N] = A[M,K] @ W[N,K]^T + bias   (nn.Linear)
// 128x128x16 tiles, cp.async double buffer, 8 warps of 64x32 warp tiles.
// ---------------------------------------------------------------------------
#define BM 128
#define BN 128
#define BKK 16
#define AP 20   // smem pitch (floats): (20*r + c) % 32 distinct for r in 0..7, c in 0..3

__global__ __launch_bounds__(256) void gemm_tf32(
    const float* __restrict__ A, const float* __restrict__ W,
    const float* __restrict__ bias, float* __restrict__ C,
    int M, int N, int K)
{
    __shared__ float As[2][BM * AP];
    __shared__ float Ws[2][BN * AP];

    const int tid  = threadIdx.x;
    const int lane = tid & 31;
    const int wid  = tid >> 5;
    const int warp_m = wid & 1;   // 0..1 (64 rows each)
    const int warp_n = wid >> 1;  // 0..3 (32 cols each)
    const int quad = lane >> 2;   // 0..7
    const int cc   = lane & 3;    // 0..3
    const int m0 = blockIdx.y * BM;
    const int n0 = blockIdx.x * BN;

    float acc[4][4][4];
#pragma unroll
    for (int mt = 0; mt < 4; mt++)
#pragma unroll
        for (int nt = 0; nt < 4; nt++)
#pragma unroll
            for (int r = 0; r < 4; r++) acc[mt][nt][r] = 0.f;

    auto issue = [&](int buf, int k0) {
#pragma unroll
        for (int e = 0; e < 2; e++) {
            int idx = tid + e * 256;          // 0..511 float4 slots
            int r   = idx >> 2;               // 0..127
            int c4  = (idx & 3) * 4;          // 0,4,8,12
            const float* gA = A + (size_t)(m0 + r) * K + k0 + c4;
            const float* gW = W + (size_t)(n0 + r) * K + k0 + c4;
            unsigned sA = smem_u32(&As[buf][r * AP + c4]);
            unsigned sW = smem_u32(&Ws[buf][r * AP + c4]);
            asm volatile("cp.async.cg.shared.global [%0], [%1], 16;" :: "r"(sA), "l"(gA));
            asm volatile("cp.async.cg.shared.global [%0], [%1], 16;" :: "r"(sW), "l"(gW));
        }
        asm volatile("cp.async.commit_group;");
    };

    const int NIT = K / BKK;   // 64
    issue(0, 0);

    for (int it = 0; it < NIT; it++) {
        if (it + 1 < NIT) {
            issue((it + 1) & 1, (it + 1) * BKK);
            asm volatile("cp.async.wait_group 1;");
        } else {
            asm volatile("cp.async.wait_group 0;");
        }
        __syncthreads();

        const float* as = As[it & 1];
        const float* ws = Ws[it & 1];

#pragma unroll
        for (int ks = 0; ks < 2; ks++) {
            unsigned af[4][4];
#pragma unroll
            for (int mt = 0; mt < 4; mt++) {
                int rb = warp_m * 64 + mt * 16;
                af[mt][0] = f2tf(as[(rb + quad)     * AP + ks * 8 + cc]);
                af[mt][1] = f2tf(as[(rb + quad + 8) * AP + ks * 8 + cc]);
                af[mt][2] = f2tf(as[(rb + quad)     * AP + ks * 8 + cc + 4]);
                af[mt][3] = f2tf(as[(rb + quad + 8) * AP + ks * 8 + cc + 4]);
            }
#pragma unroll
            for (int nt = 0; nt < 4; nt++) {
                int nb = warp_n * 32 + nt * 8;
                unsigned bf[2];
                bf[0] = f2tf(ws[(nb + quad) * AP + ks * 8 + cc]);
                bf[1] = f2tf(ws[(nb + quad) * AP + ks * 8 + cc + 4]);
#pragma unroll
                for (int mt = 0; mt < 4; mt++)
                    mma_tf32(acc[mt][nt], af[mt], bf, acc[mt][nt]);
            }
        }
        __syncthreads();
    }

    // Epilogue: bias add + float2 stores
#pragma unroll
    for (int mt = 0; mt < 4; mt++) {
        int row0 = m0 + warp_m * 64 + mt * 16 + quad;
#pragma unroll
        for (int nt = 0; nt < 4; nt++) {
            int col = n0 + warp_n * 32 + nt * 8 + 2 * cc;
            float b0 = bias[col], b1 = bias[col + 1];
            float2 v0 = make_float2(acc[mt][nt][0] + b0, acc[mt][nt][1] + b1);
            float2 v1 = make_float2(acc[mt][nt][2] + b0, acc[mt][nt][3] + b1);
            *(float2*)(C + (size_t)row0 * N + col)       = v0;
            *(float2*)(C + (size_t)(row0 + 8) * N + col) = v1;
        }
    }
}

// ---------------------------------------------------------------------------
// Flash attention with tf32 mma. Grid (T/64, B*H), 128 threads (4 warps).
// Each warp owns a 16-row query m-tile. K/V staged in smem pre-converted to
// tf32 bits. P converted C-layout -> A-layout via quad shuffles (no smem).
// ---------------------------------------------------------------------------
#define FBQ 64
#define FKV 64
#define KP  68   // (68*q + c) % 32 = 4q + c : conflict-free for S B-frags
#define VP  72   // (72*c + q) % 32 = 8c + q : conflict-free for PV B-frags

__global__ __launch_bounds__(128) void flash_tf32(
    const float* __restrict__ Q, const float* __restrict__ K,
    const float* __restrict__ V, float* __restrict__ O)
{
    __shared__ unsigned Ks[FKV * KP];
    __shared__ unsigned Vs[FKV * VP];

    const int tid  = threadIdx.x;
    const int lane = tid & 31;
    const int w    = tid >> 5;
    const int quad = lane >> 2;
    const int cc   = lane & 3;
    const int bh = blockIdx.y;
    const int b  = bh / H_;
    const int h  = bh % H_;
    const int q0 = blockIdx.x * FBQ;
    const int mrow0 = q0 + w * 16 + quad;

    // Q fragments (pre-scaled by 1/sqrt(64))
    unsigned qf[8][4];
    {
        const float* q_0 = Q + ((size_t)mrow0 * B_ + b) * D_ + h * HD_;
        const float* q_1 = Q + ((size_t)(mrow0 + 8) * B_ + b) * D_ + h * HD_;
#pragma unroll
        for (int kt = 0; kt < 8; kt++) {
            qf[kt][0] = f2tf(q_0[kt * 8 + cc]     * 0.125f);
            qf[kt][1] = f2tf(q_1[kt * 8 + cc]     * 0.125f);
            qf[kt][2] = f2tf(q_0[kt * 8 + cc + 4] * 0.125f);
            qf[kt][3] = f2tf(q_1[kt * 8 + cc + 4] * 0.125f);
        }
    }

    float m0v = -1e30f, m1v = -1e30f, l0 = 0.f, l1 = 0.f;
    float o[8][4];
#pragma unroll
    for (int dt = 0; dt < 8; dt++)
#pragma unroll
        for (int r = 0; r < 4; r++) o[dt][r] = 0.f;

    const int src0 = (lane & ~3) | (cc >> 1);
    const int src2 = src0 + 2;

    for (int s0 = 0; s0 < T_; s0 += FKV) {
        __syncthreads();
        // Stage K/V (cvt to tf32 during store)
#pragma unroll
        for (int e = 0; e < 8; e++) {
            int idx = tid + e * 128;          // 0..1023 float4 slots
            int r   = idx >> 4;               // 0..63
            int c4  = (idx & 15) * 4;         // 0..60
            size_t g = ((size_t)(s0 + r) * B_ + b) * D_ + h * HD_ + c4;
            float4 kv = *(const float4*)(K + g);
            float4 vv = *(const float4*)(V + g);
            uint4 ku = make_uint4(f2tf(kv.x), f2tf(kv.y), f2tf(kv.z), f2tf(kv.w));
            uint4 vu = make_uint4(f2tf(vv.x), f2tf(vv.y), f2tf(vv.z), f2tf(vv.w));
            *(uint4*)&Ks[r * KP + c4] = ku;
            *(uint4*)&Vs[r * VP + c4] = vu;
        }
        __syncthreads();

        // S = Q @ K^T  (per warp: 16 rows x 64 keys)
        float s[8][4];
#pragma unroll
        for (int nt = 0; nt < 8; nt++) {
#pragma unroll
            for (int r = 0; r < 4; r++) s[nt][r] = 0.f;
#pragma unroll
            for (int kt = 0; kt < 8; kt++) {
                unsigned bf[2];
                bf[0] = Ks[(nt * 8 + quad) * KP + kt * 8 + cc];
                bf[1] = Ks[(nt * 8 + quad) * KP + kt * 8 + cc + 4];
                mma_tf32(s[nt], qf[kt], bf, s[nt]);
            }
        }

        // Online softmax (two rows per thread: quad and quad+8)
        float rm0 = -1e30f, rm1 = -1e30f;
#pragma unroll
        for (int nt = 0; nt < 8; nt++) {
            rm0 = fmaxf(rm0, fmaxf(s[nt][0], s[nt][1]));
            rm1 = fmaxf(rm1, fmaxf(s[nt][2], s[nt][3]));
        }
        rm0 = fmaxf(rm0, __shfl_xor_sync(0xffffffffu, rm0, 1));
        rm0 = fmaxf(rm0, __shfl_xor_sync(0xffffffffu, rm0, 2));
        rm1 = fmaxf(rm1, __shfl_xor_sync(0xffffffffu, rm1, 1));
        rm1 = fmaxf(rm1, __shfl_xor_sync(0xffffffffu, rm1, 2));

        float mn0 = fmaxf(m0v, rm0), mn1 = fmaxf(m1v, rm1);
        float al0 = __expf(m0v - mn0), al1 = __expf(m1v - mn1);
        float ls0 = 0.f, ls1 = 0.f;
#pragma unroll
        for (int nt = 0; nt < 8; nt++) {
            s[nt][0] = __expf(s[nt][0] - mn0);
            s[nt][1] = __expf(s[nt][1] - mn0);
            s[nt][2] = __expf(s[nt][2] - mn1);
            s[nt][3] = __expf(s[nt][3] - mn1);
            ls0 += s[nt][0] + s[nt][1];
            ls1 += s[nt][2] + s[nt][3];
        }
        ls0 += __shfl_xor_sync(0xffffffffu, ls0, 1);
        ls0 += __shfl_xor_sync(0xffffffffu, ls0, 2);
        ls1 += __shfl_xor_sync(0xffffffffu, ls1, 1);
        ls1 += __shfl_xor_sync(0xffffffffu, ls1, 2);
        l0 = l0 * al0 + ls0;
        l1 = l1 * al1 + ls1;
        m0v = mn0; m1v = mn1;
#pragma unroll
        for (int dt = 0; dt < 8; dt++) {
            o[dt][0] *= al0; o[dt][1] *= al0;
            o[dt][2] *= al1; o[dt][3] *= al1;
        }

        // P: C-layout -> A-layout via quad shuffles, then tf32
        unsigned pA[8][4];
#pragma unroll
        for (int kt = 0; kt < 8; kt++) {
            float v00 = __shfl_sync(0xffffffffu, s[kt][0], src0);
            float v01 = __shfl_sync(0xffffffffu, s[kt][1], src0);
            float v20 = __shfl_sync(0xffffffffu, s[kt][2], src0);
            float v21 = __shfl_sync(0xffffffffu, s[kt][3], src0);
            float w00 = __shfl_sync(0xffffffffu, s[kt][0], src2);
            float w01 = __shfl_sync(0xffffffffu, s[kt][1], src2);
            float w20 = __shfl_sync(0xffffffffu, s[kt][2], src2);
            float w21 = __shfl_sync(0xffffffffu, s[kt][3], src2);
            pA[kt][0] = f2tf((cc & 1) ? v01 : v00);
            pA[kt][1] = f2tf((cc & 1) ? v21 : v20);
            pA[kt][2] = f2tf((cc & 1) ? w01 : w00);
            pA[kt][3] = f2tf((cc & 1) ? w21 : w20);
        }

        // O += P @ V
#pragma unroll
        for (int dt = 0; dt < 8; dt++) {
#pragma unroll
            for (int kt = 0; kt < 8; kt++) {
                unsigned bf[2];
                bf[0] = Vs[(kt * 8 + cc)     * VP + dt * 8 + quad];
                bf[1] = Vs[(kt * 8 + cc + 4) * VP + dt * 8 + quad];
                mma_tf32(o[dt], pA[kt], bf, o[dt]);
            }
        }
    }

    const float i0 = 1.f / l0, i1 = 1.f / l1;
    float* o_0 = O + ((size_t)mrow0 * B_ + b) * D_ + h * HD_;
    float* o_1 = O + ((size_t)(mrow0 + 8) * B_ + b) * D_ + h * HD_;
#pragma unroll
    for (int dt = 0; dt < 8; dt++) {
        *(float2*)(o_0 + dt * 8 + 2 * cc) = make_float2(o[dt][0] * i0, o[dt][1] * i0);
        *(float2*)(o_1 + dt * 8 + 2 * cc) = make_float2(o[dt][2] * i1, o[dt][3] * i1);
    }
}

// ---------------------------------------------------------------------------
extern "C" void kernel_launch(void* const* d_in, const int* in_sizes, int n_in,
                              void* d_out, int out_size)
{
    const float* x  = (const float*)d_in[0];
    const float* Wq = (const float*)d_in[1];
    const float* bq = (const float*)d_in[2];
    const float* Wk = (const float*)d_in[3];
    const float* bk = (const float*)d_in[4];
    const float* Wv = (const float*)d_in[5];
    const float* bv = (const float*)d_in[6];
    const float* Wo = (const float*)d_in[7];
    const float* bo = (const float*)d_in[8];
    float* out = (float*)d_out;

    float *Qb, *Kb, *Vb, *Ob;
    cudaGetSymbolAddress((void**)&Qb, g_Q);
    cudaGetSymbolAddress((void**)&Kb, g_K);
    cudaGetSymbolAddress((void**)&Vb, g_V);
    cudaGetSymbolAddress((void**)&Ob, g_O);

    dim3 gGemm(D_ / BN, M_ / BM);   // (8, 64)

    gemm_tf32<<<gGemm, 256>>>(x, Wq, bq, Qb, M_, D_, D_);
    gemm_tf32<<<gGemm, 256>>>(x, Wk, bk, Kb, M_, D_, D_);
    gemm_tf32<<<gGemm, 256>>>(x, Wv, bv, Vb, M_, D_, D_);

    flash_tf32<<<dim3(T_ / FBQ, B_ * H_), 128>>>(Qb, Kb, Vb, Ob);

    gemm_tf32<<<gGemm, 256>>>(Ob, Wo, bo, out, M_, D_, D_);
}

// round 4
// speedup vs baseline: 9.0908x; 2.0324x over previous
#include <cuda_runtime.h>
#include <cuda_fp16.h>
#include <cstdint>

#define T_  1024
#define B_  8
#define D_  1024
#define H_  16
#define HD_ 64
#define M_  (T_ * B_)

// Scratch (device globals — no runtime allocation allowed)
__device__ __half g_xh[M_ * D_];
__device__ __half g_Wqh[D_ * D_];
__device__ __half g_Wkh[D_ * D_];
__device__ __half g_Wvh[D_ * D_];
__device__ __half g_Woh[D_ * D_];
__device__ __half g_Qh[M_ * D_];
__device__ __half g_Kh[M_ * D_];
__device__ __half g_Vh[M_ * D_];
__device__ __half g_Oh[M_ * D_];

// ---------------------------------------------------------------------------
// Helpers
// ---------------------------------------------------------------------------
__device__ __forceinline__ unsigned smem_u32(const void* p) {
    return (unsigned)__cvta_generic_to_shared(p);
}

__device__ __forceinline__ void mma_f16(float d[4], const unsigned a[4],
                                        const unsigned b[2], const float c[4]) {
    asm volatile(
        "mma.sync.aligned.m16n8k16.row.col.f32.f16.f16.f32 "
        "{%0,%1,%2,%3}, {%4,%5,%6,%7}, {%8,%9}, {%10,%11,%12,%13};"
        : "=f"(d[0]), "=f"(d[1]), "=f"(d[2]), "=f"(d[3])
        : "r"(a[0]), "r"(a[1]), "r"(a[2]), "r"(a[3]),
          "r"(b[0]), "r"(b[1]),
          "f"(c[0]), "f"(c[1]), "f"(c[2]), "f"(c[3]));
}

__device__ __forceinline__ void ldsm_x4(unsigned& r0, unsigned& r1,
                                        unsigned& r2, unsigned& r3, unsigned addr) {
    asm volatile("ldmatrix.sync.aligned.m8n8.x4.shared.b16 {%0,%1,%2,%3}, [%4];"
                 : "=r"(r0), "=r"(r1), "=r"(r2), "=r"(r3) : "r"(addr));
}

__device__ __forceinline__ void ldsm_x2t(unsigned& r0, unsigned& r1, unsigned addr) {
    asm volatile("ldmatrix.sync.aligned.m8n8.x2.trans.shared.b16 {%0,%1}, [%2];"
                 : "=r"(r0), "=r"(r1) : "r"(addr));
}

__device__ __forceinline__ unsigned pack_h2(float a, float b) {
    __half2 h = __floats2half2_rn(a, b);
    return *(unsigned*)&h;
}

#define CP_ASYNC16(dst, src) \
    asm volatile("cp.async.cg.shared.global [%0], [%1], 16;" :: "r"(dst), "l"(src))
#define CP_COMMIT()  asm volatile("cp.async.commit_group;")
#define CP_WAIT(n)   asm volatile("cp.async.wait_group %0;" :: "n"(n))

// ---------------------------------------------------------------------------
// fp32 -> fp16 conversion pre-pass (4 floats -> 2 half2 per thread)
// ---------------------------------------------------------------------------
__global__ void to_half(const float4* __restrict__ s, uint2* __restrict__ d, int n4)
{
    int i = blockIdx.x * blockDim.x + threadIdx.x;
    if (i < n4) {
        float4 v = s[i];
        uint2 r;
        r.x = pack_h2(v.x, v.y);
        r.y = pack_h2(v.z, v.w);
        d[i] = r;
    }
}

// ---------------------------------------------------------------------------
// fp16 GEMM: C[M,N] = A[M,K]h @ W[N,K]h^T + bias(f32).
// 128x128 CTA tile, BK=64 halves, cp.async double buffer, 8 warps of 64x32.
// Smem pitch 72 halves -> conflict-free ldmatrix ((36r) mod 32 = 4r).
// ---------------------------------------------------------------------------
#define GP 72
#define GSTAGE_H (128 * GP)                      // halves per matrix per stage
#define GEMM_SMEM (2 * 2 * GSTAGE_H * 2)         // 73728 bytes

template<bool HALF_OUT>
__global__ __launch_bounds__(256) void gemm_f16(
    const __half* __restrict__ A, const __half* __restrict__ W,
    const float* __restrict__ bias, void* __restrict__ Cout)
{
    extern __shared__ __half sm[];

    const int tid  = threadIdx.x;
    const int lane = tid & 31;
    const int wid  = tid >> 5;
    const int warp_m = wid & 1;    // 0..1 : 64 rows
    const int warp_n = wid >> 1;   // 0..3 : 32 cols
    const int m0 = blockIdx.y * 128;
    const int n0 = blockIdx.x * 128;
    const int lrow = lane & 7;     // ldmatrix row within 8x8
    const int mi   = lane >> 3;    // ldmatrix matrix index 0..3

    float acc[4][4][4];
#pragma unroll
    for (int mt = 0; mt < 4; mt++)
#pragma unroll
        for (int nt = 0; nt < 4; nt++)
#pragma unroll
            for (int r = 0; r < 4; r++) acc[mt][nt][r] = 0.f;

    auto issue = [&](int kc, int st) {
        __half* Asm = sm + st * 2 * GSTAGE_H;
        __half* Wsm = Asm + GSTAGE_H;
#pragma unroll
        for (int i = 0; i < 8; i++) {
            int id = tid + i * 256;            // 0..2047
            if (id < 1024) {
                int r = id >> 3, c8 = id & 7;
                const __half* src = A + (size_t)(m0 + r) * D_ + kc * 64 + c8 * 8;
                CP_ASYNC16(smem_u32(Asm + r * GP + c8 * 8), src);
            } else {
                int id2 = id - 1024;
                int r = id2 >> 3, c8 = id2 & 7;
                const __half* src = W + (size_t)(n0 + r) * D_ + kc * 64 + c8 * 8;
                CP_ASYNC16(smem_u32(Wsm + r * GP + c8 * 8), src);
            }
        }
        CP_COMMIT();
    };

    const int NIT = D_ / 64;   // 16
    issue(0, 0);

    for (int kc = 0; kc < NIT; kc++) {
        if (kc + 1 < NIT) { issue(kc + 1, (kc + 1) & 1); CP_WAIT(1); }
        else              { CP_WAIT(0); }
        __syncthreads();

        const __half* Asm = sm + (kc & 1) * 2 * GSTAGE_H;
        const __half* Wsm = Asm + GSTAGE_H;
        const unsigned abase = smem_u32(Asm);
        const unsigned wbase = smem_u32(Wsm);

#pragma unroll
        for (int ks = 0; ks < 4; ks++) {
            const int colh = ks * 16 + (mi >> 1) * 8;
            unsigned af[4][4];
#pragma unroll
            for (int mt = 0; mt < 4; mt++) {
                int row = warp_m * 64 + mt * 16 + (mi & 1) * 8 + lrow;
                ldsm_x4(af[mt][0], af[mt][1], af[mt][2], af[mt][3],
                        abase + (row * GP + colh) * 2);
            }
            unsigned bf[4][2];
#pragma unroll
            for (int ntp = 0; ntp < 2; ntp++) {
                int row = warp_n * 32 + ntp * 16 + (mi & 1) * 8 + lrow;
                unsigned u0, u1, u2, u3;
                ldsm_x4(u0, u1, u2, u3, wbase + (row * GP + colh) * 2);
                bf[2 * ntp][0] = u0; bf[2 * ntp][1] = u2;
                bf[2 * ntp + 1][0] = u1; bf[2 * ntp + 1][1] = u3;
            }
#pragma unroll
            for (int mt = 0; mt < 4; mt++)
#pragma unroll
                for (int nt = 0; nt < 4; nt++)
                    mma_f16(acc[mt][nt], af[mt], bf[nt], acc[mt][nt]);
        }
        __syncthreads();
    }

    // Epilogue
    const int qrow = lane >> 2, qc = lane & 3;
#pragma unroll
    for (int mt = 0; mt < 4; mt++) {
        int r0 = m0 + warp_m * 64 + mt * 16 + qrow;
#pragma unroll
        for (int nt = 0; nt < 4; nt++) {
            int col = n0 + warp_n * 32 + nt * 8 + 2 * qc;
            float b0 = bias[col], b1 = bias[col + 1];
            if (HALF_OUT) {
                __half* C = (__half*)Cout;
                *(__half2*)(C + (size_t)r0 * D_ + col) =
                    __floats2half2_rn(acc[mt][nt][0] + b0, acc[mt][nt][1] + b1);
                *(__half2*)(C + (size_t)(r0 + 8) * D_ + col) =
                    __floats2half2_rn(acc[mt][nt][2] + b0, acc[mt][nt][3] + b1);
            } else {
                float* C = (float*)Cout;
                *(float2*)(C + (size_t)r0 * D_ + col) =
                    make_float2(acc[mt][nt][0] + b0, acc[mt][nt][1] + b1);
                *(float2*)(C + (size_t)(r0 + 8) * D_ + col) =
                    make_float2(acc[mt][nt][2] + b0, acc[mt][nt][3] + b1);
            }
        }
    }
}

// ---------------------------------------------------------------------------
// fp16 flash attention. Grid (T/64, B*H), 128 threads (4 warps).
// Warp owns 16 query rows. cp.async double-buffered K/V tiles (pure copies).
// P C-fragment maps directly to fp16 A-fragment (no shuffles).
// ---------------------------------------------------------------------------
#define FP 72                        // smem pitch (halves)
#define FTILE_H (64 * FP)

__global__ __launch_bounds__(128) void flash_f16(
    const __half* __restrict__ Q, const __half* __restrict__ K,
    const __half* __restrict__ V, __half* __restrict__ O)
{
    __shared__ __half Ks[2][FTILE_H];
    __shared__ __half Vs[2][FTILE_H];

    const int tid  = threadIdx.x;
    const int lane = tid & 31;
    const int w    = tid >> 5;
    const int quad = lane >> 2;
    const int cc   = lane & 3;
    const int lrow = lane & 7;
    const int mi   = lane >> 3;
    const int bh = blockIdx.y;
    const int b  = bh / H_;
    const int h  = bh % H_;
    const int q0 = blockIdx.x * 64;
    const int mrow0 = q0 + w * 16 + quad;

    // Q fragments, scaled by 1/8 (exact in fp16)
    unsigned qf[4][4];
    {
        const __half2 sc = __float2half2_rn(0.125f);
        const __half* q_0 = Q + ((size_t)mrow0 * B_ + b) * D_ + h * HD_;
        const __half* q_1 = q_0 + (size_t)8 * B_ * D_;
#pragma unroll
        for (int kt = 0; kt < 4; kt++) {
            __half2 a0 = __hmul2(*(const __half2*)(q_0 + kt * 16 + 2 * cc), sc);
            __half2 a1 = __hmul2(*(const __half2*)(q_1 + kt * 16 + 2 * cc), sc);
            __half2 a2 = __hmul2(*(const __half2*)(q_0 + kt * 16 + 2 * cc + 8), sc);
            __half2 a3 = __hmul2(*(const __half2*)(q_1 + kt * 16 + 2 * cc + 8), sc);
            qf[kt][0] = *(unsigned*)&a0; qf[kt][1] = *(unsigned*)&a1;
            qf[kt][2] = *(unsigned*)&a2; qf[kt][3] = *(unsigned*)&a3;
        }
    }

    float m0v = -1e30f, m1v = -1e30f, l0 = 0.f, l1 = 0.f;
    float o[8][4];
#pragma unroll
    for (int dt = 0; dt < 8; dt++)
#pragma unroll
        for (int r = 0; r < 4; r++) o[dt][r] = 0.f;

    auto issue = [&](int t, int st) {
        const int s0 = t * 64;
#pragma unroll
        for (int e = 0; e < 8; e++) {
            int idx = tid + e * 128;          // 0..1023
            if (idx < 512) {
                int r = idx >> 3, c8 = idx & 7;
                const __half* src = K + ((size_t)(s0 + r) * B_ + b) * D_ + h * HD_ + c8 * 8;
                CP_ASYNC16(smem_u32(&Ks[st][r * FP + c8 * 8]), src);
            } else {
                int id2 = idx - 512;
                int r = id2 >> 3, c8 = id2 & 7;
                const __half* src = V + ((size_t)(s0 + r) * B_ + b) * D_ + h * HD_ + c8 * 8;
                CP_ASYNC16(smem_u32(&Vs[st][r * FP + c8 * 8]), src);
            }
        }
        CP_COMMIT();
    };

    const int NT = T_ / 64;   // 16
    issue(0, 0);

    for (int t = 0; t < NT; t++) {
        if (t + 1 < NT) { issue(t + 1, (t + 1) & 1); CP_WAIT(1); }
        else            { CP_WAIT(0); }
        __syncthreads();

        const int buf = t & 1;
        const unsigned kbase = smem_u32(&Ks[buf][0]);
        const unsigned vbase = smem_u32(&Vs[buf][0]);

        // S = Q @ K^T : 8 token-tiles x 4 k-steps
        float s[8][4];
#pragma unroll
        for (int nt = 0; nt < 8; nt++)
#pragma unroll
            for (int r = 0; r < 4; r++) s[nt][r] = 0.f;

#pragma unroll
        for (int ntp = 0; ntp < 4; ntp++) {
            int row = ntp * 16 + (mi & 1) * 8 + lrow;
#pragma unroll
            for (int kt = 0; kt < 4; kt++) {
                unsigned u0, u1, u2, u3;
                ldsm_x4(u0, u1, u2, u3, kbase + (row * FP + kt * 16 + (mi >> 1) * 8) * 2);
                unsigned b0[2] = {u0, u2}, b1[2] = {u1, u3};
                mma_f16(s[2 * ntp],     qf[kt], b0, s[2 * ntp]);
                mma_f16(s[2 * ntp + 1], qf[kt], b1, s[2 * ntp + 1]);
            }
        }

        // Online softmax (rows quad and quad+8)
        float rm0 = -1e30f, rm1 = -1e30f;
#pragma unroll
        for (int nt = 0; nt < 8; nt++) {
            rm0 = fmaxf(rm0, fmaxf(s[nt][0], s[nt][1]));
            rm1 = fmaxf(rm1, fmaxf(s[nt][2], s[nt][3]));
        }
        rm0 = fmaxf(rm0, __shfl_xor_sync(0xffffffffu, rm0, 1));
        rm0 = fmaxf(rm0, __shfl_xor_sync(0xffffffffu, rm0, 2));
        rm1 = fmaxf(rm1, __shfl_xor_sync(0xffffffffu, rm1, 1));
        rm1 = fmaxf(rm1, __shfl_xor_sync(0xffffffffu, rm1, 2));

        float mn0 = fmaxf(m0v, rm0), mn1 = fmaxf(m1v, rm1);
        float al0 = __expf(m0v - mn0), al1 = __expf(m1v - mn1);
        float ls0 = 0.f, ls1 = 0.f;
#pragma unroll
        for (int nt = 0; nt < 8; nt++) {
            s[nt][0] = __expf(s[nt][0] - mn0);
            s[nt][1] = __expf(s[nt][1] - mn0);
            s[nt][2] = __expf(s[nt][2] - mn1);
            s[nt][3] = __expf(s[nt][3] - mn1);
            ls0 += s[nt][0] + s[nt][1];
            ls1 += s[nt][2] + s[nt][3];
        }
        ls0 += __shfl_xor_sync(0xffffffffu, ls0, 1);
        ls0 += __shfl_xor_sync(0xffffffffu, ls0, 2);
        ls1 += __shfl_xor_sync(0xffffffffu, ls1, 1);
        ls1 += __shfl_xor_sync(0xffffffffu, ls1, 2);
        l0 = l0 * al0 + ls0;
        l1 = l1 * al1 + ls1;
        m0v = mn0; m1v = mn1;
#pragma unroll
        for (int dt = 0; dt < 8; dt++) {
            o[dt][0] *= al0; o[dt][1] *= al0;
            o[dt][2] *= al1; o[dt][3] *= al1;
        }

        // O += P @ V : P C-layout -> A-layout is a direct half2 pack
        const int vtok = (lane & 15);
#pragma unroll
        for (int kt = 0; kt < 4; kt++) {
            unsigned a[4];
            a[0] = pack_h2(s[2 * kt][0],     s[2 * kt][1]);
            a[1] = pack_h2(s[2 * kt][2],     s[2 * kt][3]);
            a[2] = pack_h2(s[2 * kt + 1][0], s[2 * kt + 1][1]);
            a[3] = pack_h2(s[2 * kt + 1][2], s[2 * kt + 1][3]);
#pragma unroll
            for (int dt = 0; dt < 8; dt++) {
                unsigned v0, v1;
                ldsm_x2t(v0, v1, vbase + ((kt * 16 + vtok) * FP + dt * 8) * 2);
                unsigned bv[2] = {v0, v1};
                mma_f16(o[dt], a, bv, o[dt]);
            }
        }
        __syncthreads();
    }

    const float i0 = 1.f / l0, i1 = 1.f / l1;
    __half* o_0 = O + ((size_t)mrow0 * B_ + b) * D_ + h * HD_;
    __half* o_1 = o_0 + (size_t)8 * B_ * D_;
#pragma unroll
    for (int dt = 0; dt < 8; dt++) {
        *(__half2*)(o_0 + dt * 8 + 2 * cc) = __floats2half2_rn(o[dt][0] * i0, o[dt][1] * i0);
        *(__half2*)(o_1 + dt * 8 + 2 * cc) = __floats2half2_rn(o[dt][2] * i1, o[dt][3] * i1);
    }
}

// ---------------------------------------------------------------------------
extern "C" void kernel_launch(void* const* d_in, const int* in_sizes, int n_in,
                              void* d_out, int out_size)
{
    const float* x  = (const float*)d_in[0];
    const float* Wq = (const float*)d_in[1];
    const float* bq = (const float*)d_in[2];
    const float* Wk = (const float*)d_in[3];
    const float* bk = (const float*)d_in[4];
    const float* Wv = (const float*)d_in[5];
    const float* bv = (const float*)d_in[6];
    const float* Wo = (const float*)d_in[7];
    const float* bo = (const float*)d_in[8];
    float* out = (float*)d_out;

    __half *xh, *Wqh, *Wkh, *Wvh, *Woh, *Qh, *Kh, *Vh, *Oh;
    cudaGetSymbolAddress((void**)&xh,  g_xh);
    cudaGetSymbolAddress((void**)&Wqh, g_Wqh);
    cudaGetSymbolAddress((void**)&Wkh, g_Wkh);
    cudaGetSymbolAddress((void**)&Wvh, g_Wvh);
    cudaGetSymbolAddress((void**)&Woh, g_Woh);
    cudaGetSymbolAddress((void**)&Qh,  g_Qh);
    cudaGetSymbolAddress((void**)&Kh,  g_Kh);
    cudaGetSymbolAddress((void**)&Vh,  g_Vh);
    cudaGetSymbolAddress((void**)&Oh,  g_Oh);

    const int n4x = M_ * D_ / 4, n4w = D_ * D_ / 4;
    to_half<<<(n4x + 255) / 256, 256>>>((const float4*)x,  (uint2*)xh,  n4x);
    to_half<<<(n4w + 255) / 256, 256>>>((const float4*)Wq, (uint2*)Wqh, n4w);
    to_half<<<(n4w + 255) / 256, 256>>>((const float4*)Wk, (uint2*)Wkh, n4w);
    to_half<<<(n4w + 255) / 256, 256>>>((const float4*)Wv, (uint2*)Wvh, n4w);
    to_half<<<(n4w + 255) / 256, 256>>>((const float4*)Wo, (uint2*)Woh, n4w);

    cudaFuncSetAttribute(gemm_f16<true>,
                         cudaFuncAttributeMaxDynamicSharedMemorySize, GEMM_SMEM);
    cudaFuncSetAttribute(gemm_f16<false>,
                         cudaFuncAttributeMaxDynamicSharedMemorySize, GEMM_SMEM);

    dim3 gGemm(D_ / 128, M_ / 128);   // (8, 64)
    gemm_f16<true><<<gGemm, 256, GEMM_SMEM>>>(xh, Wqh, bq, Qh);
    gemm_f16<true><<<gGemm, 256, GEMM_SMEM>>>(xh, Wkh, bk, Kh);
    gemm_f16<true><<<gGemm, 256, GEMM_SMEM>>>(xh, Wvh, bv, Vh);

    flash_f16<<<dim3(T_ / 64, B_ * H_), 128>>>(Qh, Kh, Vh, Oh);

    gemm_f16<false><<<gGemm, 256, GEMM_SMEM>>>(Oh, Woh, bo, out);
}

// round 5
// speedup vs baseline: 9.9064x; 1.0897x over previous
#include <cuda_runtime.h>
#include <cuda_fp16.h>
#include <cstdint>

#define T_  1024
#define B_  8
#define D_  1024
#define H_  16
#define HD_ 64
#define M_  (T_ * B_)

// Scratch (device globals — no runtime allocation allowed)
__device__ __half g_xh[M_ * D_];
__device__ __half g_Wqkvh[3 * D_ * D_];   // packed Wq|Wk|Wv rows
__device__ __half g_Woh[D_ * D_];
__device__ __half g_QKVh[3 * M_ * D_];    // packed Q|K|V outputs
__device__ __half g_Oh[M_ * D_];

// ---------------------------------------------------------------------------
// Helpers
// ---------------------------------------------------------------------------
__device__ __forceinline__ unsigned smem_u32(const void* p) {
    return (unsigned)__cvta_generic_to_shared(p);
}

__device__ __forceinline__ void mma_f16(float d[4], const unsigned a[4],
                                        const unsigned b[2], const float c[4]) {
    asm volatile(
        "mma.sync.aligned.m16n8k16.row.col.f32.f16.f16.f32 "
        "{%0,%1,%2,%3}, {%4,%5,%6,%7}, {%8,%9}, {%10,%11,%12,%13};"
        : "=f"(d[0]), "=f"(d[1]), "=f"(d[2]), "=f"(d[3])
        : "r"(a[0]), "r"(a[1]), "r"(a[2]), "r"(a[3]),
          "r"(b[0]), "r"(b[1]),
          "f"(c[0]), "f"(c[1]), "f"(c[2]), "f"(c[3]));
}

__device__ __forceinline__ void ldsm_x4(unsigned& r0, unsigned& r1,
                                        unsigned& r2, unsigned& r3, unsigned addr) {
    asm volatile("ldmatrix.sync.aligned.m8n8.x4.shared.b16 {%0,%1,%2,%3}, [%4];"
                 : "=r"(r0), "=r"(r1), "=r"(r2), "=r"(r3) : "r"(addr));
}

__device__ __forceinline__ void ldsm_x2t(unsigned& r0, unsigned& r1, unsigned addr) {
    asm volatile("ldmatrix.sync.aligned.m8n8.x2.trans.shared.b16 {%0,%1}, [%2];"
                 : "=r"(r0), "=r"(r1) : "r"(addr));
}

__device__ __forceinline__ unsigned pack_h2(float a, float b) {
    __half2 h = __floats2half2_rn(a, b);
    return *(unsigned*)&h;
}

#define CP_ASYNC16(dst, src) \
    asm volatile("cp.async.cg.shared.global [%0], [%1], 16;" :: "r"(dst), "l"(src))
#define CP_COMMIT()  asm volatile("cp.async.commit_group;")
#define CP_WAIT(n)   asm volatile("cp.async.wait_group %0;" :: "n"(n))

// ---------------------------------------------------------------------------
// Conversion pre-passes
// ---------------------------------------------------------------------------
__global__ void to_half_x(const float4* __restrict__ s, uint2* __restrict__ d, int n4)
{
    int i = blockIdx.x * blockDim.x + threadIdx.x;
    if (i < n4) {
        float4 v = s[i];
        d[i] = make_uint2(pack_h2(v.x, v.y), pack_h2(v.z, v.w));
    }
}

// All 4 weight matrices in one launch: segments 0..2 -> packed QKV buf, 3 -> Wo buf
__global__ void to_half_w(const float4* __restrict__ wq, const float4* __restrict__ wk,
                          const float4* __restrict__ wv, const float4* __restrict__ wo,
                          uint2* __restrict__ dqkv, uint2* __restrict__ dwo)
{
    const int n4w = D_ * D_ / 4;          // 262144
    int i = blockIdx.x * blockDim.x + threadIdx.x;
    if (i >= 4 * n4w) return;
    int seg = i / n4w, j = i - seg * n4w;
    const float4* src = (seg == 0) ? wq : (seg == 1) ? wk : (seg == 2) ? wv : wo;
    float4 v = src[j];
    uint2 r = make_uint2(pack_h2(v.x, v.y), pack_h2(v.z, v.w));
    if (seg < 3) dqkv[(size_t)seg * n4w + j] = r;
    else         dwo[j] = r;
}

// ---------------------------------------------------------------------------
// fp16 GEMM: C[M,N] = A[M,K]h @ W[N,K]h^T + bias(f32).
// 128x128 CTA tile, BK=64 halves, cp.async double buffer, 8 warps of 64x32.
// Smem pitch 72 halves -> conflict-free ldmatrix.
// HALF_OUT: write fp16 into segmented QKV buffer (segment = n0>>10),
// else fp32 to a plain [M, D] float buffer.
// ---------------------------------------------------------------------------
#define GP 72
#define GSTAGE_H (128 * GP)
#define GEMM_SMEM (2 * 2 * GSTAGE_H * 2)         // 73728 bytes

template<bool HALF_OUT>
__global__ __launch_bounds__(256, 2) void gemm_f16(
    const __half* __restrict__ A, const __half* __restrict__ W,
    const float* __restrict__ b0p, const float* __restrict__ b1p,
    const float* __restrict__ b2p, void* __restrict__ Cout)
{
    extern __shared__ __half sm[];

    const int tid  = threadIdx.x;
    const int lane = tid & 31;
    const int wid  = tid >> 5;
    const int warp_m = wid & 1;
    const int warp_n = wid >> 1;
    const int m0 = blockIdx.y * 128;
    const int n0 = blockIdx.x * 128;
    const int lrow = lane & 7;
    const int mi   = lane >> 3;

    // bias/output segment (for fused QKV each 128-col block is inside one segment)
    const int seg = n0 >> 10;
    const float* bias = (seg == 0) ? b0p : (seg == 1) ? b1p : b2p;
    const int ncol0 = n0 & 1023;

    float acc[4][4][4];
#pragma unroll
    for (int mt = 0; mt < 4; mt++)
#pragma unroll
        for (int nt = 0; nt < 4; nt++)
#pragma unroll
            for (int r = 0; r < 4; r++) acc[mt][nt][r] = 0.f;

    auto issue = [&](int kc, int st) {
        __half* Asm = sm + st * 2 * GSTAGE_H;
        __half* Wsm = Asm + GSTAGE_H;
#pragma unroll
        for (int i = 0; i < 8; i++) {
            int id = tid + i * 256;
            if (id < 1024) {
                int r = id >> 3, c8 = id & 7;
                const __half* src = A + (size_t)(m0 + r) * D_ + kc * 64 + c8 * 8;
                CP_ASYNC16(smem_u32(Asm + r * GP + c8 * 8), src);
            } else {
                int id2 = id - 1024;
                int r = id2 >> 3, c8 = id2 & 7;
                const __half* src = W + (size_t)(n0 + r) * D_ + kc * 64 + c8 * 8;
                CP_ASYNC16(smem_u32(Wsm + r * GP + c8 * 8), src);
            }
        }
        CP_COMMIT();
    };

    const int NIT = D_ / 64;
    issue(0, 0);

    for (int kc = 0; kc < NIT; kc++) {
        if (kc + 1 < NIT) { issue(kc + 1, (kc + 1) & 1); CP_WAIT(1); }
        else              { CP_WAIT(0); }
        __syncthreads();

        const __half* Asm = sm + (kc & 1) * 2 * GSTAGE_H;
        const __half* Wsm = Asm + GSTAGE_H;
        const unsigned abase = smem_u32(Asm);
        const unsigned wbase = smem_u32(Wsm);

#pragma unroll
        for (int ks = 0; ks < 4; ks++) {
            const int colh = ks * 16 + (mi >> 1) * 8;
            unsigned af[4][4];
#pragma unroll
            for (int mt = 0; mt < 4; mt++) {
                int row = warp_m * 64 + mt * 16 + (mi & 1) * 8 + lrow;
                ldsm_x4(af[mt][0], af[mt][1], af[mt][2], af[mt][3],
                        abase + (row * GP + colh) * 2);
            }
            unsigned bf[4][2];
#pragma unroll
            for (int ntp = 0; ntp < 2; ntp++) {
                int row = warp_n * 32 + ntp * 16 + (mi & 1) * 8 + lrow;
                unsigned u0, u1, u2, u3;
                ldsm_x4(u0, u1, u2, u3, wbase + (row * GP + colh) * 2);
                bf[2 * ntp][0] = u0; bf[2 * ntp][1] = u2;
                bf[2 * ntp + 1][0] = u1; bf[2 * ntp + 1][1] = u3;
            }
#pragma unroll
            for (int mt = 0; mt < 4; mt++)
#pragma unroll
                for (int nt = 0; nt < 4; nt++)
                    mma_f16(acc[mt][nt], af[mt], bf[nt], acc[mt][nt]);
        }
        __syncthreads();
    }

    const int qrow = lane >> 2, qc = lane & 3;
#pragma unroll
    for (int mt = 0; mt < 4; mt++) {
        int r0 = m0 + warp_m * 64 + mt * 16 + qrow;
#pragma unroll
        for (int nt = 0; nt < 4; nt++) {
            int cl = ncol0 + warp_n * 32 + nt * 8 + 2 * qc;
            float bb0 = bias[cl], bb1 = bias[cl + 1];
            if (HALF_OUT) {
                __half* C = (__half*)Cout + (size_t)seg * M_ * D_;
                *(__half2*)(C + (size_t)r0 * D_ + cl) =
                    __floats2half2_rn(acc[mt][nt][0] + bb0, acc[mt][nt][1] + bb1);
                *(__half2*)(C + (size_t)(r0 + 8) * D_ + cl) =
                    __floats2half2_rn(acc[mt][nt][2] + bb0, acc[mt][nt][3] + bb1);
            } else {
                float* C = (float*)Cout;
                *(float2*)(C + (size_t)r0 * D_ + cl) =
                    make_float2(acc[mt][nt][0] + bb0, acc[mt][nt][1] + bb1);
                *(float2*)(C + (size_t)(r0 + 8) * D_ + cl) =
                    make_float2(acc[mt][nt][2] + bb0, acc[mt][nt][3] + bb1);
            }
        }
    }
}

// ---------------------------------------------------------------------------
// fp16 flash attention (unchanged from R4). Grid (T/64, B*H), 128 threads.
// ---------------------------------------------------------------------------
#define FP 72
#define FTILE_H (64 * FP)

__global__ __launch_bounds__(128) void flash_f16(
    const __half* __restrict__ Q, const __half* __restrict__ K,
    const __half* __restrict__ V, __half* __restrict__ O)
{
    __shared__ __half Ks[2][FTILE_H];
    __shared__ __half Vs[2][FTILE_H];

    const int tid  = threadIdx.x;
    const int lane = tid & 31;
    const int w    = tid >> 5;
    const int quad = lane >> 2;
    const int cc   = lane & 3;
    const int lrow = lane & 7;
    const int mi   = lane >> 3;
    const int bh = blockIdx.y;
    const int b  = bh / H_;
    const int h  = bh % H_;
    const int q0 = blockIdx.x * 64;
    const int mrow0 = q0 + w * 16 + quad;

    unsigned qf[4][4];
    {
        const __half2 sc = __float2half2_rn(0.125f);
        const __half* q_0 = Q + ((size_t)mrow0 * B_ + b) * D_ + h * HD_;
        const __half* q_1 = q_0 + (size_t)8 * B_ * D_;
#pragma unroll
        for (int kt = 0; kt < 4; kt++) {
            __half2 a0 = __hmul2(*(const __half2*)(q_0 + kt * 16 + 2 * cc), sc);
            __half2 a1 = __hmul2(*(const __half2*)(q_1 + kt * 16 + 2 * cc), sc);
            __half2 a2 = __hmul2(*(const __half2*)(q_0 + kt * 16 + 2 * cc + 8), sc);
            __half2 a3 = __hmul2(*(const __half2*)(q_1 + kt * 16 + 2 * cc + 8), sc);
            qf[kt][0] = *(unsigned*)&a0; qf[kt][1] = *(unsigned*)&a1;
            qf[kt][2] = *(unsigned*)&a2; qf[kt][3] = *(unsigned*)&a3;
        }
    }

    float m0v = -1e30f, m1v = -1e30f, l0 = 0.f, l1 = 0.f;
    float o[8][4];
#pragma unroll
    for (int dt = 0; dt < 8; dt++)
#pragma unroll
        for (int r = 0; r < 4; r++) o[dt][r] = 0.f;

    auto issue = [&](int t, int st) {
        const int s0 = t * 64;
#pragma unroll
        for (int e = 0; e < 8; e++) {
            int idx = tid + e * 128;
            if (idx < 512) {
                int r = idx >> 3, c8 = idx & 7;
                const __half* src = K + ((size_t)(s0 + r) * B_ + b) * D_ + h * HD_ + c8 * 8;
                CP_ASYNC16(smem_u32(&Ks[st][r * FP + c8 * 8]), src);
            } else {
                int id2 = idx - 512;
                int r = id2 >> 3, c8 = id2 & 7;
                const __half* src = V + ((size_t)(s0 + r) * B_ + b) * D_ + h * HD_ + c8 * 8;
                CP_ASYNC16(smem_u32(&Vs[st][r * FP + c8 * 8]), src);
            }
        }
        CP_COMMIT();
    };

    const int NT = T_ / 64;
    issue(0, 0);

    for (int t = 0; t < NT; t++) {
        if (t + 1 < NT) { issue(t + 1, (t + 1) & 1); CP_WAIT(1); }
        else            { CP_WAIT(0); }
        __syncthreads();

        const int buf = t & 1;
        const unsigned kbase = smem_u32(&Ks[buf][0]);
        const unsigned vbase = smem_u32(&Vs[buf][0]);

        float s[8][4];
#pragma unroll
        for (int nt = 0; nt < 8; nt++)
#pragma unroll
            for (int r = 0; r < 4; r++) s[nt][r] = 0.f;

#pragma unroll
        for (int ntp = 0; ntp < 4; ntp++) {
            int row = ntp * 16 + (mi & 1) * 8 + lrow;
#pragma unroll
            for (int kt = 0; kt < 4; kt++) {
                unsigned u0, u1, u2, u3;
                ldsm_x4(u0, u1, u2, u3, kbase + (row * FP + kt * 16 + (mi >> 1) * 8) * 2);
                unsigned b0[2] = {u0, u2}, b1[2] = {u1, u3};
                mma_f16(s[2 * ntp],     qf[kt], b0, s[2 * ntp]);
                mma_f16(s[2 * ntp + 1], qf[kt], b1, s[2 * ntp + 1]);
            }
        }

        float rm0 = -1e30f, rm1 = -1e30f;
#pragma unroll
        for (int nt = 0; nt < 8; nt++) {
            rm0 = fmaxf(rm0, fmaxf(s[nt][0], s[nt][1]));
            rm1 = fmaxf(rm1, fmaxf(s[nt][2], s[nt][3]));
        }
        rm0 = fmaxf(rm0, __shfl_xor_sync(0xffffffffu, rm0, 1));
        rm0 = fmaxf(rm0, __shfl_xor_sync(0xffffffffu, rm0, 2));
        rm1 = fmaxf(rm1, __shfl_xor_sync(0xffffffffu, rm1, 1));
        rm1 = fmaxf(rm1, __shfl_xor_sync(0xffffffffu, rm1, 2));

        float mn0 = fmaxf(m0v, rm0), mn1 = fmaxf(m1v, rm1);
        float al0 = __expf(m0v - mn0), al1 = __expf(m1v - mn1);
        float ls0 = 0.f, ls1 = 0.f;
#pragma unroll
        for (int nt = 0; nt < 8; nt++) {
            s[nt][0] = __expf(s[nt][0] - mn0);
            s[nt][1] = __expf(s[nt][1] - mn0);
            s[nt][2] = __expf(s[nt][2] - mn1);
            s[nt][3] = __expf(s[nt][3] - mn1);
            ls0 += s[nt][0] + s[nt][1];
            ls1 += s[nt][2] + s[nt][3];
        }
        ls0 += __shfl_xor_sync(0xffffffffu, ls0, 1);
        ls0 += __shfl_xor_sync(0xffffffffu, ls0, 2);
        ls1 += __shfl_xor_sync(0xffffffffu, ls1, 1);
        ls1 += __shfl_xor_sync(0xffffffffu, ls1, 2);
        l0 = l0 * al0 + ls0;
        l1 = l1 * al1 + ls1;
        m0v = mn0; m1v = mn1;
#pragma unroll
        for (int dt = 0; dt < 8; dt++) {
            o[dt][0] *= al0; o[dt][1] *= al0;
            o[dt][2] *= al1; o[dt][3] *= al1;
        }

        const int vtok = (lane & 15);
#pragma unroll
        for (int kt = 0; kt < 4; kt++) {
            unsigned a[4];
            a[0] = pack_h2(s[2 * kt][0],     s[2 * kt][1]);
            a[1] = pack_h2(s[2 * kt][2],     s[2 * kt][3]);
            a[2] = pack_h2(s[2 * kt + 1][0], s[2 * kt + 1][1]);
            a[3] = pack_h2(s[2 * kt + 1][2], s[2 * kt + 1][3]);
#pragma unroll
            for (int dt = 0; dt < 8; dt++) {
                unsigned v0, v1;
                ldsm_x2t(v0, v1, vbase + ((kt * 16 + vtok) * FP + dt * 8) * 2);
                unsigned bv[2] = {v0, v1};
                mma_f16(o[dt], a, bv, o[dt]);
            }
        }
        __syncthreads();
    }

    const float i0 = 1.f / l0, i1 = 1.f / l1;
    __half* o_0 = O + ((size_t)mrow0 * B_ + b) * D_ + h * HD_;
    __half* o_1 = o_0 + (size_t)8 * B_ * D_;
#pragma unroll
    for (int dt = 0; dt < 8; dt++) {
        *(__half2*)(o_0 + dt * 8 + 2 * cc) = __floats2half2_rn(o[dt][0] * i0, o[dt][1] * i0);
        *(__half2*)(o_1 + dt * 8 + 2 * cc) = __floats2half2_rn(o[dt][2] * i1, o[dt][3] * i1);
    }
}

// ---------------------------------------------------------------------------
extern "C" void kernel_launch(void* const* d_in, const int* in_sizes, int n_in,
                              void* d_out, int out_size)
{
    const float* x  = (const float*)d_in[0];
    const float* Wq = (const float*)d_in[1];
    const float* bq = (const float*)d_in[2];
    const float* Wk = (const float*)d_in[3];
    const float* bk = (const float*)d_in[4];
    const float* Wv = (const float*)d_in[5];
    const float* bv = (const float*)d_in[6];
    const float* Wo = (const float*)d_in[7];
    const float* bo = (const float*)d_in[8];
    float* out = (float*)d_out;

    __half *xh, *Wqkvh, *Woh, *QKVh, *Oh;
    cudaGetSymbolAddress((void**)&xh,    g_xh);
    cudaGetSymbolAddress((void**)&Wqkvh, g_Wqkvh);
    cudaGetSymbolAddress((void**)&Woh,   g_Woh);
    cudaGetSymbolAddress((void**)&QKVh,  g_QKVh);
    cudaGetSymbolAddress((void**)&Oh,    g_Oh);

    const int n4x = M_ * D_ / 4, n4w = D_ * D_ / 4;
    to_half_x<<<(n4x + 255) / 256, 256>>>((const float4*)x, (uint2*)xh, n4x);
    to_half_w<<<(4 * n4w + 255) / 256, 256>>>(
        (const float4*)Wq, (const float4*)Wk, (const float4*)Wv, (const float4*)Wo,
        (uint2*)Wqkvh, (uint2*)Woh);

    cudaFuncSetAttribute(gemm_f16<true>,
                         cudaFuncAttributeMaxDynamicSharedMemorySize, GEMM_SMEM);
    cudaFuncSetAttribute(gemm_f16<false>,
                         cudaFuncAttributeMaxDynamicSharedMemorySize, GEMM_SMEM);

    // Fused QKV projection: N = 3072
    gemm_f16<true><<<dim3(3 * D_ / 128, M_ / 128), 256, GEMM_SMEM>>>(
        xh, Wqkvh, bq, bk, bv, QKVh);

    const __half* Qh = QKVh;
    const __half* Kh = QKVh + (size_t)M_ * D_;
    const __half* Vh = QKVh + (size_t)2 * M_ * D_;
    flash_f16<<<dim3(T_ / 64, B_ * H_), 128>>>(Qh, Kh, Vh, Oh);

    // Output projection: N = 1024, fp32 out
    gemm_f16<false><<<dim3(D_ / 128, M_ / 128), 256, GEMM_SMEM>>>(
        Oh, Woh, bo, bo, bo, out);
}